// round 4
// baseline (speedup 1.0000x reference)
#include <cuda_runtime.h>
#include <cstdint>
#include <cstddef>

// ---------------------------------------------------------------------------
// AWD-LSTM forward: embed -> DeFINE -> 3x LSTM -> tied-embedding logits
// Shapes: B=32, T=128, V=32000, E=400, M=512, H=1152
// All fp32. Graph-capturable: kernel launches + D2D memcpyAsync only.
// ---------------------------------------------------------------------------

#define Bb 32
#define Tt 128
#define Vv 32000
#define Ee 400
#define Mm 512
#define Hh 1152
#define NT 4096           // B*T tokens

// ---- scratch (device globals; no allocation allowed) ----
__device__ float g_PRE[NT * 4608];      // gate preactivations (max 4*H)
__device__ float g_X0 [NT * Mm];        // DeFINE output
__device__ float g_Y0 [NT * Hh];        // layer0 output
__device__ float g_Y1 [NT * Hh];        // layer1 output
__device__ float g_Y2 [NT * Ee];        // layer2 output
__device__ float g_WT [Mm * Ee];        // define_W transposed -> [M, E]
__device__ float g_BS0[4 * Hh];
__device__ float g_BS1[4 * Hh];
__device__ float g_BS2[4 * Ee];
__device__ float g_Hbuf[2][Bb * Hh];    // ping-pong hidden state
__device__ float g_Cbuf[2][Bb * Hh];    // ping-pong cell state

// ---------------------------------------------------------------------------
// Generic fp32 GEMM:  C[M,N] = A[M,K] * B[N,K]^T + bias[N]
// A rows optionally gathered through ids (embedding lookup fusion).
// Requires M%128==0, N%64==0, K%16==0 (true for every call here).
// ---------------------------------------------------------------------------
#define BM 128
#define BN 64
#define BK 16

__global__ __launch_bounds__(256) void gemm_nt(
    const float* __restrict__ A, const float* __restrict__ Bm,
    float* __restrict__ C, const float* __restrict__ bias,
    const int* __restrict__ ids, int M, int N, int K)
{
    __shared__ float As[BK][BM + 4];
    __shared__ float Bs[BK][BN + 4];

    const int tid = threadIdx.x;
    const int m0  = blockIdx.y * BM;
    const int n0  = blockIdx.x * BN;
    const int tx  = tid & 15;   // N sub-tile (x4)
    const int ty  = tid >> 4;   // M sub-tile (x8)

    float acc[8][4] = {};

    // per-thread load assignments
    const int ar0 = tid >> 2;            // A rows 0..63
    const int ar1 = (tid + 256) >> 2;    // A rows 64..127
    const int akq = (tid & 3) << 2;      // k quad offset
    const int br  = tid >> 2;            // B rows 0..63

    const float* arow0 = ids ? (A + (size_t)ids[m0 + ar0] * K)
                             : (A + (size_t)(m0 + ar0) * K);
    const float* arow1 = ids ? (A + (size_t)ids[m0 + ar1] * K)
                             : (A + (size_t)(m0 + ar1) * K);
    const float* brow  = Bm + (size_t)(n0 + br) * K;

    for (int kt = 0; kt < K; kt += BK) {
        float4 va0 = *(const float4*)(arow0 + kt + akq);
        float4 va1 = *(const float4*)(arow1 + kt + akq);
        float4 vb  = *(const float4*)(brow  + kt + akq);

        __syncthreads();   // previous compute done before overwrite
        As[akq + 0][ar0] = va0.x;  As[akq + 1][ar0] = va0.y;
        As[akq + 2][ar0] = va0.z;  As[akq + 3][ar0] = va0.w;
        As[akq + 0][ar1] = va1.x;  As[akq + 1][ar1] = va1.y;
        As[akq + 2][ar1] = va1.z;  As[akq + 3][ar1] = va1.w;
        Bs[akq + 0][br]  = vb.x;   Bs[akq + 1][br]  = vb.y;
        Bs[akq + 2][br]  = vb.z;   Bs[akq + 3][br]  = vb.w;
        __syncthreads();

        #pragma unroll
        for (int k = 0; k < BK; ++k) {
            float4 t0 = *(const float4*)(&As[k][ty * 8]);
            float4 t1 = *(const float4*)(&As[k][ty * 8 + 4]);
            float4 t2 = *(const float4*)(&Bs[k][tx * 4]);
            float a[8] = { t0.x, t0.y, t0.z, t0.w, t1.x, t1.y, t1.z, t1.w };
            float b[4] = { t2.x, t2.y, t2.z, t2.w };
            #pragma unroll
            for (int i = 0; i < 8; ++i)
                #pragma unroll
                for (int j = 0; j < 4; ++j)
                    acc[i][j] += a[i] * b[j];
        }
    }

    float4 bv = make_float4(0.f, 0.f, 0.f, 0.f);
    if (bias) bv = *(const float4*)(bias + n0 + tx * 4);

    #pragma unroll
    for (int i = 0; i < 8; ++i) {
        float4 o;
        o.x = acc[i][0] + bv.x;  o.y = acc[i][1] + bv.y;
        o.z = acc[i][2] + bv.z;  o.w = acc[i][3] + bv.w;
        *(float4*)(C + (size_t)(m0 + ty * 8 + i) * N + n0 + tx * 4) = o;
    }
}

// ---------------------------------------------------------------------------
// One LSTM timestep.  Block = 8 hidden units x 32 batches, 256 threads.
// h_prev staged in smem transposed (stride 33 -> conflict-free broadcast).
// Whh rows streamed as warp-uniform LDG.128 (Whh resides in L2).
//   gate g[b, gate*d + j] = pre[b*T+t, gate*d+j] + sum_k h[b,k]*Whh[gate*d+j,k]
// ---------------------------------------------------------------------------
__global__ __launch_bounds__(256) void lstm_step(
    const float* __restrict__ pre,   // [B*T, 4d], m = b*T + t
    const float* __restrict__ Whh,   // [4d, d]
    const float* __restrict__ h_in, const float* __restrict__ c_in,
    float* __restrict__ h_out, float* __restrict__ c_out,
    float* __restrict__ y,           // [B, T, d]
    int t, int d)
{
    extern __shared__ float hsm[];   // [d][33]
    const int tid = threadIdx.x;

    const int total = Bb * d;
    for (int idx = tid * 4; idx < total; idx += 256 * 4) {
        float4 v = *(const float4*)(h_in + idx);
        int b = idx / d;
        int k = idx - b * d;
        hsm[(k    ) * 33 + b] = v.x;
        hsm[(k + 1) * 33 + b] = v.y;
        hsm[(k + 2) * 33 + b] = v.z;
        hsm[(k + 3) * 33 + b] = v.w;
    }
    __syncthreads();

    const int b = tid & 31;
    const int r = tid >> 5;                 // 0..7
    const int j = blockIdx.x * 8 + r;       // hidden unit

    const float* w0 = Whh + (size_t)(        j) * d;
    const float* w1 = Whh + (size_t)(    d + j) * d;
    const float* w2 = Whh + (size_t)(2 * d + j) * d;
    const float* w3 = Whh + (size_t)(3 * d + j) * d;

    float a0 = 0.f, a1 = 0.f, a2 = 0.f, a3 = 0.f;
    #pragma unroll 4
    for (int k = 0; k < d; k += 4) {
        float h0v = hsm[(k    ) * 33 + b];
        float h1v = hsm[(k + 1) * 33 + b];
        float h2v = hsm[(k + 2) * 33 + b];
        float h3v = hsm[(k + 3) * 33 + b];
        float4 q;
        q = *(const float4*)(w0 + k); a0 += q.x*h0v + q.y*h1v + q.z*h2v + q.w*h3v;
        q = *(const float4*)(w1 + k); a1 += q.x*h0v + q.y*h1v + q.z*h2v + q.w*h3v;
        q = *(const float4*)(w2 + k); a2 += q.x*h0v + q.y*h1v + q.z*h2v + q.w*h3v;
        q = *(const float4*)(w3 + k); a3 += q.x*h0v + q.y*h1v + q.z*h2v + q.w*h3v;
    }

    const float* p = pre + (size_t)(b * Tt + t) * (4 * d);
    float gi = a0 + p[            j];
    float gf = a1 + p[    d + j];
    float gg = a2 + p[2 * d + j];
    float go = a3 + p[3 * d + j];

    float si = 1.f / (1.f + expf(-gi));
    float sf = 1.f / (1.f + expf(-gf));
    float so = 1.f / (1.f + expf(-go));
    float cn = sf * c_in[b * d + j] + si * tanhf(gg);
    float hn = so * tanhf(cn);

    c_out[b * d + j] = cn;
    h_out[b * d + j] = hn;
    y[(size_t)(b * Tt + t) * d + j] = hn;
}

// ---- small helpers ----
__global__ void transpose_def(const float* __restrict__ W, float* __restrict__ WT)
{
    int idx = blockIdx.x * 256 + threadIdx.x;     // WT[n*E + k] = W[k*M + n]
    if (idx < Mm * Ee) {
        int n = idx / Ee, k = idx - n * Ee;
        WT[idx] = W[k * Mm + n];
    }
}

__global__ void add_bias(const float* __restrict__ a, const float* __restrict__ b,
                         float* __restrict__ o, int n)
{
    int i = blockIdx.x * 256 + threadIdx.x;
    if (i < n) o[i] = a[i] + b[i];
}

// ---------------------------------------------------------------------------
extern "C" void kernel_launch(void* const* d_in, const int* in_sizes, int n_in,
                              void* d_out, int out_size)
{
    (void)in_sizes; (void)n_in; (void)out_size;

    const int*   ids  = (const int*)  d_in[0];
    const float* emb  = (const float*)d_in[1];
    const float* dW   = (const float*)d_in[2];
    const float* db   = (const float*)d_in[3];
    const float* Wih0 = (const float*)d_in[4];
    const float* Whh0 = (const float*)d_in[5];
    const float* bih0 = (const float*)d_in[6];
    const float* bhh0 = (const float*)d_in[7];
    const float* h00  = (const float*)d_in[8];
    const float* c00  = (const float*)d_in[9];
    const float* Wih1 = (const float*)d_in[10];
    const float* Whh1 = (const float*)d_in[11];
    const float* bih1 = (const float*)d_in[12];
    const float* bhh1 = (const float*)d_in[13];
    const float* h01  = (const float*)d_in[14];
    const float* c01  = (const float*)d_in[15];
    const float* Wih2 = (const float*)d_in[16];
    const float* Whh2 = (const float*)d_in[17];
    const float* bih2 = (const float*)d_in[18];
    const float* bhh2 = (const float*)d_in[19];
    const float* h02  = (const float*)d_in[20];
    const float* c02  = (const float*)d_in[21];
    float* out = (float*)d_out;

    float *PRE, *X0, *Y0, *Y1, *Y2, *WT, *BS0, *BS1, *BS2, *Hb, *Cb;
    cudaGetSymbolAddress((void**)&PRE, g_PRE);
    cudaGetSymbolAddress((void**)&X0,  g_X0);
    cudaGetSymbolAddress((void**)&Y0,  g_Y0);
    cudaGetSymbolAddress((void**)&Y1,  g_Y1);
    cudaGetSymbolAddress((void**)&Y2,  g_Y2);
    cudaGetSymbolAddress((void**)&WT,  g_WT);
    cudaGetSymbolAddress((void**)&BS0, g_BS0);
    cudaGetSymbolAddress((void**)&BS1, g_BS1);
    cudaGetSymbolAddress((void**)&BS2, g_BS2);
    cudaGetSymbolAddress((void**)&Hb,  g_Hbuf);
    cudaGetSymbolAddress((void**)&Cb,  g_Cbuf);
    float* Hp[2] = { Hb, Hb + Bb * Hh };
    float* Cp[2] = { Cb, Cb + Bb * Hh };

    cudaFuncSetAttribute(lstm_step,
                         cudaFuncAttributeMaxDynamicSharedMemorySize, 160000);

    // output offsets (floats)
    const size_t OFF_H0 = (size_t)Bb * Tt * Vv;          // 131072000
    const size_t OFF_C0 = OFF_H0 + (size_t)Bb * Hh;
    const size_t OFF_H1 = OFF_C0 + (size_t)Bb * Hh;
    const size_t OFF_C1 = OFF_H1 + (size_t)Bb * Hh;
    const size_t OFF_H2 = OFF_C1 + (size_t)Bb * Hh;
    const size_t OFF_C2 = OFF_H2 + (size_t)Bb * Ee;

    // ---- prep ----
    transpose_def<<<(Mm * Ee + 255) / 256, 256>>>(dW, WT);
    add_bias<<<(4 * Hh + 255) / 256, 256>>>(bih0, bhh0, BS0, 4 * Hh);
    add_bias<<<(4 * Hh + 255) / 256, 256>>>(bih1, bhh1, BS1, 4 * Hh);
    add_bias<<<(4 * Ee + 255) / 256, 256>>>(bih2, bhh2, BS2, 4 * Ee);

    // ---- embed + DeFINE:  X0 = emb[ids] @ define_W + define_b ----
    gemm_nt<<<dim3(Mm / BN, NT / BM), 256>>>(emb, WT, X0, db, ids, NT, Mm, Ee);

    // ================= layer 0 (512 -> 1152) =================
    gemm_nt<<<dim3(4 * Hh / BN, NT / BM), 256>>>(X0, Wih0, PRE, BS0, nullptr,
                                                 NT, 4 * Hh, Mm);
    cudaMemcpyAsync(Hp[0], h00, (size_t)Bb * Hh * 4, cudaMemcpyDeviceToDevice, 0);
    cudaMemcpyAsync(Cp[0], c00, (size_t)Bb * Hh * 4, cudaMemcpyDeviceToDevice, 0);
    for (int t = 0; t < Tt; ++t) {
        int s = t & 1;
        lstm_step<<<Hh / 8, 256, Hh * 33 * 4>>>(PRE, Whh0, Hp[s], Cp[s],
                                                Hp[1 - s], Cp[1 - s], Y0, t, Hh);
    }
    cudaMemcpyAsync(out + OFF_H0, Hp[0], (size_t)Bb * Hh * 4, cudaMemcpyDeviceToDevice, 0);
    cudaMemcpyAsync(out + OFF_C0, Cp[0], (size_t)Bb * Hh * 4, cudaMemcpyDeviceToDevice, 0);

    // ================= layer 1 (1152 -> 1152) =================
    gemm_nt<<<dim3(4 * Hh / BN, NT / BM), 256>>>(Y0, Wih1, PRE, BS1, nullptr,
                                                 NT, 4 * Hh, Hh);
    cudaMemcpyAsync(Hp[0], h01, (size_t)Bb * Hh * 4, cudaMemcpyDeviceToDevice, 0);
    cudaMemcpyAsync(Cp[0], c01, (size_t)Bb * Hh * 4, cudaMemcpyDeviceToDevice, 0);
    for (int t = 0; t < Tt; ++t) {
        int s = t & 1;
        lstm_step<<<Hh / 8, 256, Hh * 33 * 4>>>(PRE, Whh1, Hp[s], Cp[s],
                                                Hp[1 - s], Cp[1 - s], Y1, t, Hh);
    }
    cudaMemcpyAsync(out + OFF_H1, Hp[0], (size_t)Bb * Hh * 4, cudaMemcpyDeviceToDevice, 0);
    cudaMemcpyAsync(out + OFF_C1, Cp[0], (size_t)Bb * Hh * 4, cudaMemcpyDeviceToDevice, 0);

    // ================= layer 2 (1152 -> 400) =================
    gemm_nt<<<dim3(4 * Ee / BN, NT / BM), 256>>>(Y1, Wih2, PRE, BS2, nullptr,
                                                 NT, 4 * Ee, Hh);
    cudaMemcpyAsync(Hp[0], h02, (size_t)Bb * Ee * 4, cudaMemcpyDeviceToDevice, 0);
    cudaMemcpyAsync(Cp[0], c02, (size_t)Bb * Ee * 4, cudaMemcpyDeviceToDevice, 0);
    for (int t = 0; t < Tt; ++t) {
        int s = t & 1;
        lstm_step<<<Ee / 8, 256, Ee * 33 * 4>>>(PRE, Whh2, Hp[s], Cp[s],
                                                Hp[1 - s], Cp[1 - s], Y2, t, Ee);
    }
    cudaMemcpyAsync(out + OFF_H2, Hp[0], (size_t)Bb * Ee * 4, cudaMemcpyDeviceToDevice, 0);
    cudaMemcpyAsync(out + OFF_C2, Cp[0], (size_t)Bb * Ee * 4, cudaMemcpyDeviceToDevice, 0);

    // ---- tied-embedding logits: out = Y2 @ emb^T ----
    gemm_nt<<<dim3(Vv / BN, NT / BM), 256>>>(Y2, emb, out, nullptr, nullptr,
                                             NT, Vv, Ee);
}